// round 14
// baseline (speedup 1.0000x reference)
#include <cuda_runtime.h>
#include <cuda_bf16.h>
#include <cuda_fp16.h>
#include <math.h>
#include <stdint.h>

// ---------------------------------------------------------------------------
// Problem constants
// ---------------------------------------------------------------------------
#define BATCH   32
#define CIN     512
#define COUT    512
#define HEADS   8
#define DH      64
#define S       1024
#define NKV     320
#define NKVP    384
#define QKVC    1536
#define KDIM    512

// ---------------------------------------------------------------------------
// Scratch (device globals)
// ---------------------------------------------------------------------------
__device__ __align__(16) __half g_kvp[(size_t)BATCH * 1024 * NKVP];   // kv pre-sigmoid fp16
__device__ float g_pool[(size_t)BATCH * CIN * NKV];
__device__ __align__(16) __half g_qh [(size_t)BATCH * CIN * S];
__device__ __align__(16) __half g_x  [(size_t)BATCH * S * KDIM];
__device__ __align__(16) __half g_xp [(size_t)BATCH * NKVP * KDIM];
__device__ __align__(16) __half g_kh [(size_t)BATCH * HEADS * NKV * DH];
__device__ __align__(16) __half g_vh [(size_t)BATCH * HEADS * DH * NKV];
__device__ __align__(16) __half g_at [(size_t)BATCH * S * CIN];
__device__ __align__(16) __half g_wq [(size_t)QKVC * KDIM];
__device__ __align__(16) __half g_wo [(size_t)COUT * KDIM];

// ---------------------------------------------------------------------------
// PTX helpers
// ---------------------------------------------------------------------------
__device__ __forceinline__ uint32_t smem_u32(const void* p) {
    uint32_t a;
    asm("{ .reg .u64 t; cvta.to.shared.u64 t, %1; cvt.u32.u64 %0, t; }"
        : "=r"(a) : "l"(p));
    return a;
}
__device__ __forceinline__ void cpasync16(uint32_t s, const void* g) {
    asm volatile("cp.async.cg.shared.global [%0], [%1], 16;" :: "r"(s), "l"(g));
}
#define CP_COMMIT() asm volatile("cp.async.commit_group;" ::: "memory")
#define CP_WAIT(N)  asm volatile("cp.async.wait_group %0;" :: "n"(N) : "memory")

#define LDSM_X4(r, addr) \
    asm volatile("ldmatrix.sync.aligned.m8n8.x4.shared.b16 {%0,%1,%2,%3}, [%4];" \
                 : "=r"((r)[0]), "=r"((r)[1]), "=r"((r)[2]), "=r"((r)[3]) : "r"(addr))
#define LDSM_X4_T(r, addr) \
    asm volatile("ldmatrix.sync.aligned.m8n8.x4.trans.shared.b16 {%0,%1,%2,%3}, [%4];" \
                 : "=r"((r)[0]), "=r"((r)[1]), "=r"((r)[2]), "=r"((r)[3]) : "r"(addr))

__device__ __forceinline__ void mma_f16(float* d, const uint32_t* a,
                                        uint32_t b0, uint32_t b1) {
    asm volatile(
        "mma.sync.aligned.m16n8k16.row.col.f32.f16.f16.f32 "
        "{%0,%1,%2,%3}, {%4,%5,%6,%7}, {%8,%9}, {%0,%1,%2,%3};"
        : "+f"(d[0]), "+f"(d[1]), "+f"(d[2]), "+f"(d[3])
        : "r"(a[0]), "r"(a[1]), "r"(a[2]), "r"(a[3]), "r"(b0), "r"(b1));
}

// ---------------------------------------------------------------------------
// Weight prep
// ---------------------------------------------------------------------------
__global__ void cvt_wqkv_kernel(const float* __restrict__ a, __half* __restrict__ h)
{
    int i = blockIdx.x * 256 + threadIdx.x;
    if (i < QKVC * KDIM) {
        const float sc = (i < CIN * KDIM) ? 0.125f : 1.f;
        h[i] = __float2half_rn(a[i] * sc);
    }
}
__global__ void cvt_kernel(const float* __restrict__ a, __half* __restrict__ h, int n)
{
    int i = blockIdx.x * 256 + threadIdx.x;
    if (i < n) h[i] = __float2half_rn(a[i]);
}

__global__ void __launch_bounds__(256) tsplit_kernel(
    const float* __restrict__ x, __half* __restrict__ o)
{
    __shared__ float t[32][33];
    const int n0 = blockIdx.x * 32, k0 = blockIdx.y * 32, b = blockIdx.z;
    const int tx = threadIdx.x, ty = threadIdx.y;
    const float* src = x + ((size_t)b * KDIM + k0) * S + n0;
#pragma unroll
    for (int i = 0; i < 4; i++)
        t[ty + 8 * i][tx] = src[(size_t)(ty + 8 * i) * S + tx];
    __syncthreads();
    __half* d = o + ((size_t)b * S + n0) * KDIM + k0;
#pragma unroll
    for (int i = 0; i < 4; i++)
        d[(size_t)(ty + 8 * i) * KDIM + tx] = __float2half_rn(t[tx][ty + 8 * i]);
}

// ---------------------------------------------------------------------------
// Pool x -> pooled fp32 [b][c][320].  All phases use 8 threads/output with
// warp-shuffle reduction (no serial 32-loops).
// ---------------------------------------------------------------------------
__global__ void __launch_bounds__(256) pool_x_kernel(
    const float* __restrict__ x, float* __restrict__ pooled)
{
    const int bc = blockIdx.x;
    const float* src = x + (size_t)bc * S;
    float* dst = pooled + (size_t)bc * NKV;

    __shared__ float ts[S];
    const int tid = threadIdx.x;
    ((float4*)ts)[tid] = ((const float4*)src)[tid];
    __syncthreads();

    const int g = tid >> 3;     // output index 0..31
    const int q = tid & 7;      // reducer lane 0..7

    // h-mean: row g, 8 threads each sum 4 strided elements
    {
        float s = ts[g * 32 + q] + ts[g * 32 + q + 8]
                + ts[g * 32 + q + 16] + ts[g * 32 + q + 24];
        s += __shfl_xor_sync(0xffffffffu, s, 1);
        s += __shfl_xor_sync(0xffffffffu, s, 2);
        s += __shfl_xor_sync(0xffffffffu, s, 4);
        if (q == 0) dst[g] = s * (1.f / 32.f);
    }
    // w-mean: col g
    {
        float s = ts[q * 32 + g] + ts[(q + 8) * 32 + g]
                + ts[(q + 16) * 32 + g] + ts[(q + 24) * 32 + g];
        s += __shfl_xor_sync(0xffffffffu, s, 1);
        s += __shfl_xor_sync(0xffffffffu, s, 2);
        s += __shfl_xor_sync(0xffffffffu, s, 4);
        if (q == 0) dst[32 + g] = s * (1.f / 32.f);
    }
    // 2x2 avg: one output per thread
    {
        const int ph = tid >> 4, pw = tid & 15;
        const float s = ts[(2 * ph) * 32 + 2 * pw] + ts[(2 * ph) * 32 + 2 * pw + 1]
                      + ts[(2 * ph + 1) * 32 + 2 * pw] + ts[(2 * ph + 1) * 32 + 2 * pw + 1];
        dst[64 + tid] = s * 0.25f;
    }
}

// ---------------------------------------------------------------------------
// Transpose pooled [b][c][320] -> xp fp16 [b][n][c]; rows 320..383 zero.
// ---------------------------------------------------------------------------
__global__ void __launch_bounds__(256) xpose_kernel(
    const float* __restrict__ pooled, __half* __restrict__ xp)
{
    __shared__ float t[32][33];
    const int c0 = blockIdx.x * 32, n0 = blockIdx.y * 32, b = blockIdx.z;
    const int tx = threadIdx.x, ty = threadIdx.y;
    const bool valid = (n0 < NKV);
    if (valid) {
        const float* src = pooled + ((size_t)b * CIN + c0) * NKV + n0;
#pragma unroll
        for (int i = 0; i < 4; i++)
            t[ty + 8 * i][tx] = src[(size_t)(ty + 8 * i) * NKV + tx];
    }
    __syncthreads();
    __half* d = xp + ((size_t)b * NKVP + n0) * KDIM + c0;
#pragma unroll
    for (int i = 0; i < 4; i++)
        d[(size_t)(ty + 8 * i) * KDIM + tx] =
            __float2half_rn(valid ? t[tx][ty + 8 * i] : 0.f);
}

// ---------------------------------------------------------------------------
// HMMA fp16 single-weight batched GEMM (unchanged from R12/13).
// ---------------------------------------------------------------------------
#define T_B     10240
#define STG_SZ  20480
#define GSMEM   (4 * STG_SZ)

__global__ void __launch_bounds__(256, 2) gemm_mma_kernel(
    const __half* __restrict__ A, const __half* __restrict__ B,
    float* __restrict__ C, __half* __restrict__ Ch,
    const float* __restrict__ bias, int Ntot)
{
    extern __shared__ char smem[];
    const uint32_t sbase = smem_u32(smem);

    const int tid = threadIdx.x;
    const int n0 = blockIdx.x * 128;
    const int m0 = blockIdx.y * 128;
    const int M  = gridDim.y * 128;
    const size_t bo = (size_t)blockIdx.z * Ntot * KDIM;
    const size_t co = (size_t)blockIdx.z * M * Ntot;

    const __half* Bb = B + bo;

    const int wid = tid >> 5, lane = tid & 31;
    const int wm = (wid & 3) * 32, wn = (wid >> 2) * 64;
    const uint32_t aoff = (uint32_t)((wm + (lane & 15)) * 80 + (lane >> 4) * 16);
    const uint32_t boff = (uint32_t)(T_B + (wn + (lane & 15)) * 80 + (lane >> 4) * 16);

    float acc[2][8][4];
#pragma unroll
    for (int f = 0; f < 2; f++)
#pragma unroll
        for (int j = 0; j < 8; j++)
#pragma unroll
            for (int r = 0; r < 4; r++) acc[f][j][r] = 0.f;

#define ISSUE(cc, st) do {                                                     \
        const uint32_t sp = sbase + (st) * STG_SZ;                             \
        _Pragma("unroll")                                                      \
        for (int it = 0; it < 2; it++) {                                       \
            const int idx = tid + it * 256;                                    \
            const int row = idx >> 2, ch = idx & 3;                            \
            const uint32_t so = (uint32_t)(row * 80 + ch * 16);                \
            const size_t ga = (size_t)(m0 + row) * KDIM + (cc) * 32 + ch * 8;  \
            const size_t gb = (size_t)(n0 + row) * KDIM + (cc) * 32 + ch * 8;  \
            cpasync16(sp + so,       A  + ga);                                 \
            cpasync16(sp + T_B + so, Bb + gb);                                 \
        }                                                                      \
    } while (0)

    ISSUE(0, 0); CP_COMMIT();
    ISSUE(1, 1); CP_COMMIT();
    ISSUE(2, 2); CP_COMMIT();

    const int NCH = KDIM / 32;
    for (int c = 0; c < NCH; c++) {
        CP_WAIT(2);
        __syncthreads();
        if (c + 3 < NCH) ISSUE(c + 3, (c + 3) & 3);
        CP_COMMIT();

        const uint32_t sa = sbase + (uint32_t)((c & 3) * STG_SZ);
#pragma unroll
        for (int kk = 0; kk < 2; kk++) {
            uint32_t ah[2][4];
            LDSM_X4(ah[0], sa + aoff + kk * 32);
            LDSM_X4(ah[1], sa + aoff + kk * 32 + 1280);
#pragma unroll
            for (int g = 0; g < 4; g++) {
                uint32_t bh[4];
                LDSM_X4(bh, sa + boff + kk * 32 + g * 1280);
#pragma unroll
                for (int f = 0; f < 2; f++) {
                    mma_f16(acc[f][2 * g],     ah[f], bh[0], bh[2]);
                    mma_f16(acc[f][2 * g + 1], ah[f], bh[1], bh[3]);
                }
            }
        }
    }
#undef ISSUE

    if (Ch) {
#pragma unroll
        for (int f = 0; f < 2; f++) {
            const int r0 = m0 + wm + f * 16 + (lane >> 2);
            __half* cp0 = Ch + co + (size_t)r0 * Ntot;
            __half* cp1 = cp0 + (size_t)8 * Ntot;
#pragma unroll
            for (int j = 0; j < 8; j++) {
                const int col = n0 + wn + j * 8 + (lane & 3) * 2;
                *(__half2*)(cp0 + col) = __floats2half2_rn(acc[f][j][0], acc[f][j][1]);
                *(__half2*)(cp1 + col) = __floats2half2_rn(acc[f][j][2], acc[f][j][3]);
            }
        }
    } else {
#pragma unroll
        for (int f = 0; f < 2; f++) {
            const int r0 = m0 + wm + f * 16 + (lane >> 2);
            const float bv0 = bias ? bias[r0] : 0.f;
            const float bv1 = bias ? bias[r0 + 8] : 0.f;
            float* cp0 = C + co + (size_t)r0 * Ntot;
            float* cp1 = cp0 + (size_t)8 * Ntot;
#pragma unroll
            for (int j = 0; j < 8; j++) {
                const int col = n0 + wn + j * 8 + (lane & 3) * 2;
                *(float2*)(cp0 + col) = make_float2(acc[f][j][0] + bv0, acc[f][j][1] + bv0);
                *(float2*)(cp1 + col) = make_float2(acc[f][j][2] + bv1, acc[f][j][3] + bv1);
            }
        }
    }
}

// ---------------------------------------------------------------------------
// kv gates (fp16 input).
// ---------------------------------------------------------------------------
__global__ void __launch_bounds__(256) kvgate_k_kernel(
    const __half* __restrict__ kvp, __half* __restrict__ khg)
{
    __shared__ float t[64 * 65];
    const int n0 = blockIdx.x * 64;
    const int h = blockIdx.y, b = blockIdx.z;
    const int tid = threadIdx.x;

#pragma unroll
    for (int j = 0; j < 16; j++) {
        const int idx = tid + j * 256;
        const int d = idx >> 6, np = idx & 63;
        t[np * 65 + d] = __half2float(
            kvp[((size_t)(b * 1024 + h * 64 + d)) * NKVP + n0 + np]);
    }
    __syncthreads();

    __half* dst = khg + ((size_t)(b * HEADS + h) * NKV + n0) * DH;
#pragma unroll
    for (int j = 0; j < 16; j++) {
        const int idx = tid + j * 256;
        const int np = idx >> 6, d = idx & 63;
        const float v = t[np * 65 + d];
        dst[(size_t)np * DH + d] = __float2half_rn(1.f / (1.f + __expf(-v)));
    }
}

__global__ void __launch_bounds__(256) kvgate_v_kernel(
    const __half* __restrict__ kvp, __half* __restrict__ vhg)
{
    const int c = blockIdx.x;
    const int b = blockIdx.y;
    const __half* src = kvp + ((size_t)(b * 1024 + 512 + c)) * NKVP;
    __half* dst = vhg + ((size_t)((b * HEADS + (c >> 6)) * DH + (c & 63))) * NKV;
    for (int n = threadIdx.x; n < NKV; n += 256) {
        const float v = __half2float(src[n]);
        dst[n] = __float2half_rn(1.f / (1.f + __expf(-v)));
    }
}

// ---------------------------------------------------------------------------
// MMA attention v3 (unchanged from R13): TQ=64, register softmax, 2 CTAs/SM.
// ---------------------------------------------------------------------------
#define TQ       64
#define Q_ROW    144
#define K_ROW    144
#define V_ROW    656
#define P_ROW    656
#define A_Q      0
#define A_K      9216
#define A_V      9216
#define A_P      55296
#define A_MX     97280
#define A_SM2    97792
#define A_INV    98304
#define ATTN2_SMEM 98560

__global__ void __launch_bounds__(256, 2) attn_mma_kernel(
    const __half* __restrict__ qh,
    const __half* __restrict__ khg, const __half* __restrict__ vhg,
    const float* __restrict__ pos,
    __half* __restrict__ att)
{
    extern __shared__ char sm[];
    const uint32_t sb = smem_u32(sm);
    const int b = blockIdx.z, hd = blockIdx.y;
    const int s0 = blockIdx.x * TQ;
    const int tid = threadIdx.x, wid = tid >> 5, lane = tid & 31;

    {
        const char* kh = (const char*)(khg + (size_t)(b * HEADS + hd) * NKV * DH);
#pragma unroll
        for (int i = 0; i < 10; i++) {
            const int c = tid + i * 256;
            cpasync16(sb + A_K + (c >> 3) * K_ROW + (c & 7) * 16,
                      kh + (size_t)c * 16);
        }
    }
    {
        const __half* qg = qh + ((size_t)b * CIN + hd * DH) * S + s0;
#pragma unroll
        for (int i = 0; i < 2; i++) {
            const int c = tid + i * 256;
            const int row = c >> 3, ch = c & 7;
            cpasync16(sb + A_Q + row * Q_ROW + ch * 16,
                      qg + (size_t)row * S + ch * 8);
        }
    }
    CP_COMMIT();
    CP_WAIT(0);
    __syncthreads();

    const int mw = wid & 3;
    const int nw = wid >> 2;
    const int n0w = nw * 160;
    const int r0 = mw * 16 + (lane >> 2);

    float acc[20][4];
#pragma unroll
    for (int t = 0; t < 20; t++) {
        acc[t][0] = 0.f; acc[t][1] = 0.f; acc[t][2] = 0.f; acc[t][3] = 0.f;
    }

    {
        const uint32_t qaddr0 = sb + A_Q
            + (uint32_t)(((lane & 7) + ((lane >> 4) << 3)) * Q_ROW
            + (mw * 16 + (((lane >> 3) & 1) << 3)) * 2);
#pragma unroll
        for (int k = 0; k < 4; k++) {
            uint32_t ah[4];
            LDSM_X4_T(ah, qaddr0 + k * 16 * Q_ROW);
#pragma unroll
            for (int jn = 0; jn < 10; jn++) {
                uint32_t bh[4];
                LDSM_X4(bh, sb + A_K + (n0w + jn * 16 + (lane & 15)) * K_ROW
                            + (lane >> 4) * 16 + k * 32);
                mma_f16(acc[2 * jn],     ah, bh[0], bh[2]);
                mma_f16(acc[2 * jn + 1], ah, bh[1], bh[3]);
            }
        }
    }
    __syncthreads();

    {
        const char* vh = (const char*)(vhg + (size_t)(b * HEADS + hd) * DH * NKV);
#pragma unroll
        for (int i = 0; i < 10; i++) {
            const int c = tid + i * 256;
            const int d = c / 40, o = c % 40;
            cpasync16(sb + A_V + d * V_ROW + o * 16, vh + (size_t)c * 16);
        }
        CP_COMMIT();
    }

    float mx0 = -1e30f, mx1 = -1e30f;
    {
        const float* pr0 = pos + (size_t)(s0 + r0) * NKV;
        const float* pr1 = pr0 + (size_t)8 * NKV;
#pragma unroll
        for (int g = 0; g < 20; g++) {
            const int jn = g >> 1, t = g & 1;
            const int n = n0w + jn * 16 + t * 8 + (lane & 3) * 2;
            const float2 p0 = *(const float2*)(pr0 + n);
            const float2 p1 = *(const float2*)(pr1 + n);
            acc[g][0] += p0.x; acc[g][1] += p0.y;
            acc[g][2] += p1.x; acc[g][3] += p1.y;
            mx0 = fmaxf(mx0, fmaxf(acc[g][0], acc[g][1]));
            mx1 = fmaxf(mx1, fmaxf(acc[g][2], acc[g][3]));
        }
    }
    mx0 = fmaxf(mx0, __shfl_xor_sync(0xffffffffu, mx0, 1));
    mx0 = fmaxf(mx0, __shfl_xor_sync(0xffffffffu, mx0, 2));
    mx1 = fmaxf(mx1, __shfl_xor_sync(0xffffffffu, mx1, 1));
    mx1 = fmaxf(mx1, __shfl_xor_sync(0xffffffffu, mx1, 2));
    if ((lane & 3) == 0) {
        *(float*)(sm + A_MX + (nw * 64 + r0) * 4)     = mx0;
        *(float*)(sm + A_MX + (nw * 64 + r0 + 8) * 4) = mx1;
    }
    __syncthreads();
    const float gm0 = fmaxf(*(const float*)(sm + A_MX + r0 * 4),
                            *(const float*)(sm + A_MX + (64 + r0) * 4));
    const float gm1 = fmaxf(*(const float*)(sm + A_MX + (r0 + 8) * 4),
                            *(const float*)(sm + A_MX + (64 + r0 + 8) * 4));

    float sm0 = 0.f, sm1 = 0.f;
#pragma unroll
    for (int g = 0; g < 20; g++) {
        acc[g][0] = __expf(acc[g][0] - gm0);
        acc[g][1] = __expf(acc[g][1] - gm0);
        acc[g][2] = __expf(acc[g][2] - gm1);
        acc[g][3] = __expf(acc[g][3] - gm1);
        sm0 += acc[g][0] + acc[g][1];
        sm1 += acc[g][2] + acc[g][3];
    }
    sm0 += __shfl_xor_sync(0xffffffffu, sm0, 1);
    sm0 += __shfl_xor_sync(0xffffffffu, sm0, 2);
    sm1 += __shfl_xor_sync(0xffffffffu, sm1, 1);
    sm1 += __shfl_xor_sync(0xffffffffu, sm1, 2);
    if ((lane & 3) == 0) {
        *(float*)(sm + A_SM2 + (nw * 64 + r0) * 4)     = sm0;
        *(float*)(sm + A_SM2 + (nw * 64 + r0 + 8) * 4) = sm1;
    }
    __syncthreads();
    if (nw == 0 && (lane & 3) == 0) {
        const float i0 = 1.f / (*(const float*)(sm + A_SM2 + r0 * 4)
                              + *(const float*)(sm + A_SM2 + (64 + r0) * 4));
        const float i1 = 1.f / (*(const float*)(sm + A_SM2 + (r0 + 8) * 4)
                              + *(const float*)(sm + A_SM2 + (64 + r0 + 8) * 4));
        *(float*)(sm + A_INV + r0 * 4)       = i0;
        *(float*)(sm + A_INV + (r0 + 8) * 4) = i1;
    }

#pragma unroll
    for (int g = 0; g < 20; g++) {
        const int jn = g >> 1, t = g & 1;
        const int n = n0w + jn * 16 + t * 8 + (lane & 3) * 2;
        *(__half2*)(sm + A_P + r0 * P_ROW + n * 2) =
            __floats2half2_rn(acc[g][0], acc[g][1]);
        *(__half2*)(sm + A_P + (r0 + 8) * P_ROW + n * 2) =
            __floats2half2_rn(acc[g][2], acc[g][3]);
    }
    CP_WAIT(0);
    __syncthreads();

    {
        const int dw = nw;
        float oa[4][4];
#pragma unroll
        for (int t = 0; t < 4; t++) {
            oa[t][0] = 0.f; oa[t][1] = 0.f; oa[t][2] = 0.f; oa[t][3] = 0.f;
        }
#pragma unroll
        for (int k = 0; k < 20; k++) {
            uint32_t pa[4], v0[4], v1[4];
            LDSM_X4(pa, sb + A_P + (mw * 16 + (lane & 15)) * P_ROW
                        + (lane >> 4) * 16 + k * 32);
            const uint32_t va = sb + A_V + (dw * 32 + (lane & 15)) * V_ROW
                              + (lane >> 4) * 16 + k * 32;
            LDSM_X4(v0, va);
            LDSM_X4(v1, va + 16 * V_ROW);
            mma_f16(oa[0], pa, v0[0], v0[2]);
            mma_f16(oa[1], pa, v0[1], v0[3]);
            mma_f16(oa[2], pa, v1[0], v1[2]);
            mma_f16(oa[3], pa, v1[1], v1[3]);
        }
        const float inv0 = *(const float*)(sm + A_INV + r0 * 4);
        const float inv1 = *(const float*)(sm + A_INV + (r0 + 8) * 4);
        const size_t ro0 = ((size_t)b * S + s0 + r0) * CIN + hd * DH;
        const size_t ro1 = ro0 + (size_t)8 * CIN;
#pragma unroll
        for (int jt = 0; jt < 4; jt++) {
            const int col = dw * 32 + jt * 8 + (lane & 3) * 2;
            __half2 h0 = __floats2half2_rn(oa[jt][0] * inv0, oa[jt][1] * inv0);
            __half2 h1 = __floats2half2_rn(oa[jt][2] * inv1, oa[jt][3] * inv1);
            *(__half2*)(att + ro0 + col) = h0;
            *(__half2*)(att + ro1 + col) = h1;
        }
    }
}

// ---------------------------------------------------------------------------
// Launch
// ---------------------------------------------------------------------------
extern "C" void kernel_launch(void* const* d_in, const int* in_sizes, int n_in,
                              void* d_out, int out_size)
{
    const float* x     = (const float*)d_in[0];
    const float* Wqkv  = (const float*)d_in[1];
    const float* Wout  = (const float*)d_in[2];
    const float* bout  = (const float*)d_in[3];
    const float* pos   = (const float*)d_in[4];
    float* out = (float*)d_out;

    float *p_pool;
    __half *p_kvp, *p_qh, *p_x, *p_xp, *p_kh, *p_vh, *p_at, *p_wq, *p_wo;
    cudaGetSymbolAddress((void**)&p_kvp,  g_kvp);
    cudaGetSymbolAddress((void**)&p_pool, g_pool);
    cudaGetSymbolAddress((void**)&p_qh,   g_qh);
    cudaGetSymbolAddress((void**)&p_x,    g_x);
    cudaGetSymbolAddress((void**)&p_xp,   g_xp);
    cudaGetSymbolAddress((void**)&p_kh,   g_kh);
    cudaGetSymbolAddress((void**)&p_vh,   g_vh);
    cudaGetSymbolAddress((void**)&p_at,   g_at);
    cudaGetSymbolAddress((void**)&p_wq,   g_wq);
    cudaGetSymbolAddress((void**)&p_wo,   g_wo);

    cudaFuncSetAttribute(gemm_mma_kernel,
                         cudaFuncAttributeMaxDynamicSharedMemorySize, GSMEM);
    cudaFuncSetAttribute(attn_mma_kernel,
                         cudaFuncAttributeMaxDynamicSharedMemorySize, ATTN2_SMEM);

    // 0) operand prep
    cvt_wqkv_kernel<<<(QKVC * KDIM + 255) / 256, 256>>>(Wqkv, p_wq);
    cvt_kernel<<<(COUT * KDIM + 255) / 256, 256>>>(Wout, p_wo, COUT * KDIM);
    tsplit_kernel<<<dim3(S / 32, KDIM / 32, BATCH), dim3(32, 8)>>>(x, p_x);
    pool_x_kernel<<<BATCH * CIN, 256>>>(x, p_pool);
    xpose_kernel<<<dim3(KDIM / 32, NKVP / 32, BATCH), dim3(32, 8)>>>(p_pool, p_xp);

    // 1) Q = (0.125*Wq) @ x^T -> fp16 [B,512,1024]
    gemm_mma_kernel<<<dim3(S / 128, CIN / 128, BATCH), 256, GSMEM>>>(
        p_wq, p_x, nullptr, p_qh, nullptr, S);

    // 2) kv_pre = Wkv @ xp^T -> fp16 [B,1024,384]
    gemm_mma_kernel<<<dim3(NKVP / 128, 1024 / 128, BATCH), 256, GSMEM>>>(
        p_wq + (size_t)CIN * KDIM, p_xp, nullptr, p_kvp, nullptr, NKVP);

    // 3) sigmoid gates -> K (tiled transpose), V (elementwise)
    kvgate_k_kernel<<<dim3(NKV / 64, HEADS, BATCH), 256>>>(p_kvp, p_kh);
    kvgate_v_kernel<<<dim3(512, BATCH), 256>>>(p_kvp, p_vh);

    // 4) tensor-core attention -> att fp16 [B,S,C]
    attn_mma_kernel<<<dim3(S / TQ, HEADS, BATCH), 256, ATTN2_SMEM>>>(
        p_qh, p_kh, p_vh, pos, p_at);

    // 5) out = Wout @ att^T + bout   [B,512,1024]
    gemm_mma_kernel<<<dim3(S / 128, COUT / 128, BATCH), 256, GSMEM>>>(
        p_wo, p_at, out, nullptr, bout, S);
}

// round 15
// speedup vs baseline: 1.0355x; 1.0355x over previous
#include <cuda_runtime.h>
#include <cuda_bf16.h>
#include <cuda_fp16.h>
#include <math.h>
#include <stdint.h>

// ---------------------------------------------------------------------------
// Problem constants
// ---------------------------------------------------------------------------
#define BATCH   32
#define CIN     512
#define COUT    512
#define HEADS   8
#define DH      64
#define S       1024
#define NKV     320
#define NKVP    384
#define QKVC    1536
#define KDIM    512

// ---------------------------------------------------------------------------
// Scratch (device globals)
// ---------------------------------------------------------------------------
__device__ __align__(16) __half g_kvp[(size_t)BATCH * CIN * NKVP]; // K pre-sigmoid fp16
__device__ float g_pool[(size_t)BATCH * CIN * NKV];
__device__ __align__(16) __half g_qh [(size_t)BATCH * CIN * S];
__device__ __align__(16) __half g_x  [(size_t)BATCH * S * KDIM];
__device__ __align__(16) __half g_xp [(size_t)BATCH * NKVP * KDIM];
__device__ __align__(16) __half g_kh [(size_t)BATCH * HEADS * NKV * DH];
__device__ __align__(16) __half g_vh [(size_t)BATCH * HEADS * DH * NKV];
__device__ __align__(16) __half g_at [(size_t)BATCH * S * CIN];
__device__ __align__(16) __half g_wq [(size_t)QKVC * KDIM];
__device__ __align__(16) __half g_wo [(size_t)COUT * KDIM];

// ---------------------------------------------------------------------------
// PTX helpers
// ---------------------------------------------------------------------------
__device__ __forceinline__ uint32_t smem_u32(const void* p) {
    uint32_t a;
    asm("{ .reg .u64 t; cvta.to.shared.u64 t, %1; cvt.u32.u64 %0, t; }"
        : "=r"(a) : "l"(p));
    return a;
}
__device__ __forceinline__ void cpasync16(uint32_t s, const void* g) {
    asm volatile("cp.async.cg.shared.global [%0], [%1], 16;" :: "r"(s), "l"(g));
}
#define CP_COMMIT() asm volatile("cp.async.commit_group;" ::: "memory")
#define CP_WAIT(N)  asm volatile("cp.async.wait_group %0;" :: "n"(N) : "memory")

#define LDSM_X4(r, addr) \
    asm volatile("ldmatrix.sync.aligned.m8n8.x4.shared.b16 {%0,%1,%2,%3}, [%4];" \
                 : "=r"((r)[0]), "=r"((r)[1]), "=r"((r)[2]), "=r"((r)[3]) : "r"(addr))
#define LDSM_X4_T(r, addr) \
    asm volatile("ldmatrix.sync.aligned.m8n8.x4.trans.shared.b16 {%0,%1,%2,%3}, [%4];" \
                 : "=r"((r)[0]), "=r"((r)[1]), "=r"((r)[2]), "=r"((r)[3]) : "r"(addr))

__device__ __forceinline__ void mma_f16(float* d, const uint32_t* a,
                                        uint32_t b0, uint32_t b1) {
    asm volatile(
        "mma.sync.aligned.m16n8k16.row.col.f32.f16.f16.f32 "
        "{%0,%1,%2,%3}, {%4,%5,%6,%7}, {%8,%9}, {%0,%1,%2,%3};"
        : "+f"(d[0]), "+f"(d[1]), "+f"(d[2]), "+f"(d[3])
        : "r"(a[0]), "r"(a[1]), "r"(a[2]), "r"(a[3]), "r"(b0), "r"(b1));
}
__device__ __forceinline__ float sigmoidf_(float x) {
    return 1.f / (1.f + __expf(-x));
}

// ---------------------------------------------------------------------------
// Weight prep
// ---------------------------------------------------------------------------
__global__ void cvt_wqkv_kernel(const float* __restrict__ a, __half* __restrict__ h)
{
    int i = blockIdx.x * 256 + threadIdx.x;
    if (i < QKVC * KDIM) {
        const float sc = (i < CIN * KDIM) ? 0.125f : 1.f;
        h[i] = __float2half_rn(a[i] * sc);
    }
}
__global__ void cvt_kernel(const float* __restrict__ a, __half* __restrict__ h, int n)
{
    int i = blockIdx.x * 256 + threadIdx.x;
    if (i < n) h[i] = __float2half_rn(a[i]);
}

__global__ void __launch_bounds__(256) tsplit_kernel(
    const float* __restrict__ x, __half* __restrict__ o)
{
    __shared__ float t[32][33];
    const int n0 = blockIdx.x * 32, k0 = blockIdx.y * 32, b = blockIdx.z;
    const int tx = threadIdx.x, ty = threadIdx.y;
    const float* src = x + ((size_t)b * KDIM + k0) * S + n0;
#pragma unroll
    for (int i = 0; i < 4; i++)
        t[ty + 8 * i][tx] = src[(size_t)(ty + 8 * i) * S + tx];
    __syncthreads();
    __half* d = o + ((size_t)b * S + n0) * KDIM + k0;
#pragma unroll
    for (int i = 0; i < 4; i++)
        d[(size_t)(ty + 8 * i) * KDIM + tx] = __float2half_rn(t[tx][ty + 8 * i]);
}

// ---------------------------------------------------------------------------
// Pool x -> pooled fp32 [b][c][320]  (R13 version, measured fastest)
// ---------------------------------------------------------------------------
__global__ void __launch_bounds__(256) pool_x_kernel(
    const float* __restrict__ x, float* __restrict__ pooled)
{
    const int bc = blockIdx.x;
    const float* src = x + (size_t)bc * S;
    float* dst = pooled + (size_t)bc * NKV;

    __shared__ float ts[S];
    const int tid = threadIdx.x;
    ((float4*)ts)[tid] = ((const float4*)src)[tid];
    __syncthreads();

    if (tid < 32) {
        float s = 0.f;
#pragma unroll
        for (int w = 0; w < 32; w++) s += ts[tid * 32 + w];
        dst[tid] = s * (1.f / 32.f);
    } else if (tid < 64) {
        const int w = tid - 32;
        float s = 0.f;
#pragma unroll
        for (int hh = 0; hh < 32; hh++) s += ts[hh * 32 + w];
        dst[tid] = s * (1.f / 32.f);
    }
    {
        const int ph = tid >> 4, pw = tid & 15;
        const float s = ts[(2 * ph) * 32 + 2 * pw] + ts[(2 * ph) * 32 + 2 * pw + 1]
                      + ts[(2 * ph + 1) * 32 + 2 * pw] + ts[(2 * ph + 1) * 32 + 2 * pw + 1];
        dst[64 + tid] = s * 0.25f;
    }
}

// ---------------------------------------------------------------------------
// Transpose pooled [b][c][320] -> xp fp16 [b][n][c]; rows 320..383 zero.
// ---------------------------------------------------------------------------
__global__ void __launch_bounds__(256) xpose_kernel(
    const float* __restrict__ pooled, __half* __restrict__ xp)
{
    __shared__ float t[32][33];
    const int c0 = blockIdx.x * 32, n0 = blockIdx.y * 32, b = blockIdx.z;
    const int tx = threadIdx.x, ty = threadIdx.y;
    const bool valid = (n0 < NKV);
    if (valid) {
        const float* src = pooled + ((size_t)b * CIN + c0) * NKV + n0;
#pragma unroll
        for (int i = 0; i < 4; i++)
            t[ty + 8 * i][tx] = src[(size_t)(ty + 8 * i) * NKV + tx];
    }
    __syncthreads();
    __half* d = xp + ((size_t)b * NKVP + n0) * KDIM + c0;
#pragma unroll
    for (int i = 0; i < 4; i++)
        d[(size_t)(ty + 8 * i) * KDIM + tx] =
            __float2half_rn(valid ? t[tx][ty + 8 * i] : 0.f);
}

// ---------------------------------------------------------------------------
// HMMA fp16 single-weight batched GEMM.  Epilogue modes:
//   0: fp32 + bias -> C            (output projection)
//   1: fp16 -> Ch                  (Q)
//   2: kv: rows<512 -> kvp fp16 (K pre-act); rows>=512 -> sigmoid -> V [b,h,d,n]
// ---------------------------------------------------------------------------
#define T_B     10240
#define STG_SZ  20480
#define GSMEM   (4 * STG_SZ)

__global__ void __launch_bounds__(256, 2) gemm_mma_kernel(
    const __half* __restrict__ A, const __half* __restrict__ B,
    float* __restrict__ C, __half* __restrict__ Ch,
    __half* __restrict__ Vh,
    const float* __restrict__ bias, int Ntot, int mode)
{
    extern __shared__ char smem[];
    const uint32_t sbase = smem_u32(smem);

    const int tid = threadIdx.x;
    const int n0 = blockIdx.x * 128;
    const int m0 = blockIdx.y * 128;
    const int M  = gridDim.y * 128;
    const int bz = blockIdx.z;
    const size_t bo = (size_t)bz * Ntot * KDIM;

    const __half* Bb = B + bo;

    const int wid = tid >> 5, lane = tid & 31;
    const int wm = (wid & 3) * 32, wn = (wid >> 2) * 64;
    const uint32_t aoff = (uint32_t)((wm + (lane & 15)) * 80 + (lane >> 4) * 16);
    const uint32_t boff = (uint32_t)(T_B + (wn + (lane & 15)) * 80 + (lane >> 4) * 16);

    float acc[2][8][4];
#pragma unroll
    for (int f = 0; f < 2; f++)
#pragma unroll
        for (int j = 0; j < 8; j++)
#pragma unroll
            for (int r = 0; r < 4; r++) acc[f][j][r] = 0.f;

#define ISSUE(cc, st) do {                                                     \
        const uint32_t sp = sbase + (st) * STG_SZ;                             \
        _Pragma("unroll")                                                      \
        for (int it = 0; it < 2; it++) {                                       \
            const int idx = tid + it * 256;                                    \
            const int row = idx >> 2, ch = idx & 3;                            \
            const uint32_t so = (uint32_t)(row * 80 + ch * 16);                \
            const size_t ga = (size_t)(m0 + row) * KDIM + (cc) * 32 + ch * 8;  \
            const size_t gb = (size_t)(n0 + row) * KDIM + (cc) * 32 + ch * 8;  \
            cpasync16(sp + so,       A  + ga);                                 \
            cpasync16(sp + T_B + so, Bb + gb);                                 \
        }                                                                      \
    } while (0)

    ISSUE(0, 0); CP_COMMIT();
    ISSUE(1, 1); CP_COMMIT();
    ISSUE(2, 2); CP_COMMIT();

    const int NCH = KDIM / 32;
    for (int c = 0; c < NCH; c++) {
        CP_WAIT(2);
        __syncthreads();
        if (c + 3 < NCH) ISSUE(c + 3, (c + 3) & 3);
        CP_COMMIT();

        const uint32_t sa = sbase + (uint32_t)((c & 3) * STG_SZ);
#pragma unroll
        for (int kk = 0; kk < 2; kk++) {
            uint32_t ah[2][4];
            LDSM_X4(ah[0], sa + aoff + kk * 32);
            LDSM_X4(ah[1], sa + aoff + kk * 32 + 1280);
#pragma unroll
            for (int g = 0; g < 4; g++) {
                uint32_t bh[4];
                LDSM_X4(bh, sa + boff + kk * 32 + g * 1280);
#pragma unroll
                for (int f = 0; f < 2; f++) {
                    mma_f16(acc[f][2 * g],     ah[f], bh[0], bh[2]);
                    mma_f16(acc[f][2 * g + 1], ah[f], bh[1], bh[3]);
                }
            }
        }
    }
#undef ISSUE

    if (mode == 1) {
        const size_t co = (size_t)bz * M * Ntot;
#pragma unroll
        for (int f = 0; f < 2; f++) {
            const int r0 = m0 + wm + f * 16 + (lane >> 2);
            __half* cp0 = Ch + co + (size_t)r0 * Ntot;
            __half* cp1 = cp0 + (size_t)8 * Ntot;
#pragma unroll
            for (int j = 0; j < 8; j++) {
                const int col = n0 + wn + j * 8 + (lane & 3) * 2;
                *(__half2*)(cp0 + col) = __floats2half2_rn(acc[f][j][0], acc[f][j][1]);
                *(__half2*)(cp1 + col) = __floats2half2_rn(acc[f][j][2], acc[f][j][3]);
            }
        }
    } else if (mode == 0) {
        const size_t co = (size_t)bz * M * Ntot;
#pragma unroll
        for (int f = 0; f < 2; f++) {
            const int r0 = m0 + wm + f * 16 + (lane >> 2);
            const float bv0 = bias ? bias[r0] : 0.f;
            const float bv1 = bias ? bias[r0 + 8] : 0.f;
            float* cp0 = C + co + (size_t)r0 * Ntot;
            float* cp1 = cp0 + (size_t)8 * Ntot;
#pragma unroll
            for (int j = 0; j < 8; j++) {
                const int col = n0 + wn + j * 8 + (lane & 3) * 2;
                *(float2*)(cp0 + col) = make_float2(acc[f][j][0] + bv0, acc[f][j][1] + bv0);
                *(float2*)(cp1 + col) = make_float2(acc[f][j][2] + bv1, acc[f][j][3] + bv1);
            }
        }
    } else {
        // mode 2: kv.  rows < 512 -> kvp fp16 [b][c][384]; rows >= 512 ->
        // sigmoid -> V [b][h][d][n] (row-major in n, col<320 only).
#pragma unroll
        for (int f = 0; f < 2; f++) {
#pragma unroll
            for (int half = 0; half < 2; half++) {
                const int rg = m0 + wm + f * 16 + half * 8 + (lane >> 2);
                const float a0 = acc[f][0][2 * half];   // placeholder; handled below
                (void)a0;
                if (rg < 512) {
                    __half* cp = g_kvp + ((size_t)bz * CIN + rg) * NKVP;
#pragma unroll
                    for (int j = 0; j < 8; j++) {
                        const int col = n0 + wn + j * 8 + (lane & 3) * 2;
                        *(__half2*)(cp + col) =
                            __floats2half2_rn(acc[f][j][2 * half], acc[f][j][2 * half + 1]);
                    }
                } else {
                    const int vc = rg - 512;
                    __half* cp = Vh + ((size_t)(bz * HEADS + (vc >> 6)) * DH + (vc & 63)) * NKV;
#pragma unroll
                    for (int j = 0; j < 8; j++) {
                        const int col = n0 + wn + j * 8 + (lane & 3) * 2;
                        if (col < NKV) {
                            *(__half2*)(cp + col) = __floats2half2_rn(
                                sigmoidf_(acc[f][j][2 * half]),
                                sigmoidf_(acc[f][j][2 * half + 1]));
                        }
                    }
                }
            }
        }
    }
}

// ---------------------------------------------------------------------------
// K gate: smem 64x64 tile transpose from kvp (K channels only).
// ---------------------------------------------------------------------------
__global__ void __launch_bounds__(256) kvgate_k_kernel(
    const __half* __restrict__ kvp, __half* __restrict__ khg)
{
    __shared__ float t[64 * 65];
    const int n0 = blockIdx.x * 64;
    const int h = blockIdx.y, b = blockIdx.z;
    const int tid = threadIdx.x;

#pragma unroll
    for (int j = 0; j < 16; j++) {
        const int idx = tid + j * 256;
        const int d = idx >> 6, np = idx & 63;
        t[np * 65 + d] = __half2float(
            kvp[((size_t)(b * CIN + h * 64 + d)) * NKVP + n0 + np]);
    }
    __syncthreads();

    __half* dst = khg + ((size_t)(b * HEADS + h) * NKV + n0) * DH;
#pragma unroll
    for (int j = 0; j < 16; j++) {
        const int idx = tid + j * 256;
        const int np = idx >> 6, d = idx & 63;
        dst[(size_t)np * DH + d] = __float2half_rn(sigmoidf_(t[np * 65 + d]));
    }
}

// ---------------------------------------------------------------------------
// MMA attention v3 (unchanged from R13): TQ=64, register softmax, 2 CTAs/SM.
// ---------------------------------------------------------------------------
#define TQ       64
#define Q_ROW    144
#define K_ROW    144
#define V_ROW    656
#define P_ROW    656
#define A_Q      0
#define A_K      9216
#define A_V      9216
#define A_P      55296
#define A_MX     97280
#define A_SM2    97792
#define A_INV    98304
#define ATTN2_SMEM 98560

__global__ void __launch_bounds__(256, 2) attn_mma_kernel(
    const __half* __restrict__ qh,
    const __half* __restrict__ khg, const __half* __restrict__ vhg,
    const float* __restrict__ pos,
    __half* __restrict__ att)
{
    extern __shared__ char sm[];
    const uint32_t sb = smem_u32(sm);
    const int b = blockIdx.z, hd = blockIdx.y;
    const int s0 = blockIdx.x * TQ;
    const int tid = threadIdx.x, wid = tid >> 5, lane = tid & 31;

    {
        const char* kh = (const char*)(khg + (size_t)(b * HEADS + hd) * NKV * DH);
#pragma unroll
        for (int i = 0; i < 10; i++) {
            const int c = tid + i * 256;
            cpasync16(sb + A_K + (c >> 3) * K_ROW + (c & 7) * 16,
                      kh + (size_t)c * 16);
        }
    }
    {
        const __half* qg = qh + ((size_t)b * CIN + hd * DH) * S + s0;
#pragma unroll
        for (int i = 0; i < 2; i++) {
            const int c = tid + i * 256;
            const int row = c >> 3, ch = c & 7;
            cpasync16(sb + A_Q + row * Q_ROW + ch * 16,
                      qg + (size_t)row * S + ch * 8);
        }
    }
    CP_COMMIT();
    CP_WAIT(0);
    __syncthreads();

    const int mw = wid & 3;
    const int nw = wid >> 2;
    const int n0w = nw * 160;
    const int r0 = mw * 16 + (lane >> 2);

    float acc[20][4];
#pragma unroll
    for (int t = 0; t < 20; t++) {
        acc[t][0] = 0.f; acc[t][1] = 0.f; acc[t][2] = 0.f; acc[t][3] = 0.f;
    }

    {
        const uint32_t qaddr0 = sb + A_Q
            + (uint32_t)(((lane & 7) + ((lane >> 4) << 3)) * Q_ROW
            + (mw * 16 + (((lane >> 3) & 1) << 3)) * 2);
#pragma unroll
        for (int k = 0; k < 4; k++) {
            uint32_t ah[4];
            LDSM_X4_T(ah, qaddr0 + k * 16 * Q_ROW);
#pragma unroll
            for (int jn = 0; jn < 10; jn++) {
                uint32_t bh[4];
                LDSM_X4(bh, sb + A_K + (n0w + jn * 16 + (lane & 15)) * K_ROW
                            + (lane >> 4) * 16 + k * 32);
                mma_f16(acc[2 * jn],     ah, bh[0], bh[2]);
                mma_f16(acc[2 * jn + 1], ah, bh[1], bh[3]);
            }
        }
    }
    __syncthreads();

    {
        const char* vh = (const char*)(vhg + (size_t)(b * HEADS + hd) * DH * NKV);
#pragma unroll
        for (int i = 0; i < 10; i++) {
            const int c = tid + i * 256;
            const int d = c / 40, o = c % 40;
            cpasync16(sb + A_V + d * V_ROW + o * 16, vh + (size_t)c * 16);
        }
        CP_COMMIT();
    }

    float mx0 = -1e30f, mx1 = -1e30f;
    {
        const float* pr0 = pos + (size_t)(s0 + r0) * NKV;
        const float* pr1 = pr0 + (size_t)8 * NKV;
#pragma unroll
        for (int g = 0; g < 20; g++) {
            const int jn = g >> 1, t = g & 1;
            const int n = n0w + jn * 16 + t * 8 + (lane & 3) * 2;
            const float2 p0 = *(const float2*)(pr0 + n);
            const float2 p1 = *(const float2*)(pr1 + n);
            acc[g][0] += p0.x; acc[g][1] += p0.y;
            acc[g][2] += p1.x; acc[g][3] += p1.y;
            mx0 = fmaxf(mx0, fmaxf(acc[g][0], acc[g][1]));
            mx1 = fmaxf(mx1, fmaxf(acc[g][2], acc[g][3]));
        }
    }
    mx0 = fmaxf(mx0, __shfl_xor_sync(0xffffffffu, mx0, 1));
    mx0 = fmaxf(mx0, __shfl_xor_sync(0xffffffffu, mx0, 2));
    mx1 = fmaxf(mx1, __shfl_xor_sync(0xffffffffu, mx1, 1));
    mx1 = fmaxf(mx1, __shfl_xor_sync(0xffffffffu, mx1, 2));
    if ((lane & 3) == 0) {
        *(float*)(sm + A_MX + (nw * 64 + r0) * 4)     = mx0;
        *(float*)(sm + A_MX + (nw * 64 + r0 + 8) * 4) = mx1;
    }
    __syncthreads();
    const float gm0 = fmaxf(*(const float*)(sm + A_MX + r0 * 4),
                            *(const float*)(sm + A_MX + (64 + r0) * 4));
    const float gm1 = fmaxf(*(const float*)(sm + A_MX + (r0 + 8) * 4),
                            *(const float*)(sm + A_MX + (64 + r0 + 8) * 4));

    float sm0 = 0.f, sm1 = 0.f;
#pragma unroll
    for (int g = 0; g < 20; g++) {
        acc[g][0] = __expf(acc[g][0] - gm0);
        acc[g][1] = __expf(acc[g][1] - gm0);
        acc[g][2] = __expf(acc[g][2] - gm1);
        acc[g][3] = __expf(acc[g][3] - gm1);
        sm0 += acc[g][0] + acc[g][1];
        sm1 += acc[g][2] + acc[g][3];
    }
    sm0 += __shfl_xor_sync(0xffffffffu, sm0, 1);
    sm0 += __shfl_xor_sync(0xffffffffu, sm0, 2);
    sm1 += __shfl_xor_sync(0xffffffffu, sm1, 1);
    sm1 += __shfl_xor_sync(0xffffffffu, sm1, 2);
    if ((lane & 3) == 0) {
        *(float*)(sm + A_SM2 + (nw * 64 + r0) * 4)     = sm0;
        *(float*)(sm + A_SM2 + (nw * 64 + r0 + 8) * 4) = sm1;
    }
    __syncthreads();
    if (nw == 0 && (lane & 3) == 0) {
        const float i0 = 1.f / (*(const float*)(sm + A_SM2 + r0 * 4)
                              + *(const float*)(sm + A_SM2 + (64 + r0) * 4));
        const float i1 = 1.f / (*(const float*)(sm + A_SM2 + (r0 + 8) * 4)
                              + *(const float*)(sm + A_SM2 + (64 + r0 + 8) * 4));
        *(float*)(sm + A_INV + r0 * 4)       = i0;
        *(float*)(sm + A_INV + (r0 + 8) * 4) = i1;
    }

#pragma unroll
    for (int g = 0; g < 20; g++) {
        const int jn = g >> 1, t = g & 1;
        const int n = n0w + jn * 16 + t * 8 + (lane & 3) * 2;
        *(__half2*)(sm + A_P + r0 * P_ROW + n * 2) =
            __floats2half2_rn(acc[g][0], acc[g][1]);
        *(__half2*)(sm + A_P + (r0 + 8) * P_ROW + n * 2) =
            __floats2half2_rn(acc[g][2], acc[g][3]);
    }
    CP_WAIT(0);
    __syncthreads();

    {
        const int dw = nw;
        float oa[4][4];
#pragma unroll
        for (int t = 0; t < 4; t++) {
            oa[t][0] = 0.f; oa[t][1] = 0.f; oa[t][2] = 0.f; oa[t][3] = 0.f;
        }
#pragma unroll
        for (int k = 0; k < 20; k++) {
            uint32_t pa[4], v0[4], v1[4];
            LDSM_X4(pa, sb + A_P + (mw * 16 + (lane & 15)) * P_ROW
                        + (lane >> 4) * 16 + k * 32);
            const uint32_t va = sb + A_V + (dw * 32 + (lane & 15)) * V_ROW
                              + (lane >> 4) * 16 + k * 32;
            LDSM_X4(v0, va);
            LDSM_X4(v1, va + 16 * V_ROW);
            mma_f16(oa[0], pa, v0[0], v0[2]);
            mma_f16(oa[1], pa, v0[1], v0[3]);
            mma_f16(oa[2], pa, v1[0], v1[2]);
            mma_f16(oa[3], pa, v1[1], v1[3]);
        }
        const float inv0 = *(const float*)(sm + A_INV + r0 * 4);
        const float inv1 = *(const float*)(sm + A_INV + (r0 + 8) * 4);
        const size_t ro0 = ((size_t)b * S + s0 + r0) * CIN + hd * DH;
        const size_t ro1 = ro0 + (size_t)8 * CIN;
#pragma unroll
        for (int jt = 0; jt < 4; jt++) {
            const int col = dw * 32 + jt * 8 + (lane & 3) * 2;
            __half2 h0 = __floats2half2_rn(oa[jt][0] * inv0, oa[jt][1] * inv0);
            __half2 h1 = __floats2half2_rn(oa[jt][2] * inv1, oa[jt][3] * inv1);
            *(__half2*)(att + ro0 + col) = h0;
            *(__half2*)(att + ro1 + col) = h1;
        }
    }
}

// ---------------------------------------------------------------------------
// Launch
// ---------------------------------------------------------------------------
extern "C" void kernel_launch(void* const* d_in, const int* in_sizes, int n_in,
                              void* d_out, int out_size)
{
    const float* x     = (const float*)d_in[0];
    const float* Wqkv  = (const float*)d_in[1];
    const float* Wout  = (const float*)d_in[2];
    const float* bout  = (const float*)d_in[3];
    const float* pos   = (const float*)d_in[4];
    float* out = (float*)d_out;

    float *p_pool;
    __half *p_kvp, *p_qh, *p_x, *p_xp, *p_kh, *p_vh, *p_at, *p_wq, *p_wo;
    cudaGetSymbolAddress((void**)&p_kvp,  g_kvp);
    cudaGetSymbolAddress((void**)&p_pool, g_pool);
    cudaGetSymbolAddress((void**)&p_qh,   g_qh);
    cudaGetSymbolAddress((void**)&p_x,    g_x);
    cudaGetSymbolAddress((void**)&p_xp,   g_xp);
    cudaGetSymbolAddress((void**)&p_kh,   g_kh);
    cudaGetSymbolAddress((void**)&p_vh,   g_vh);
    cudaGetSymbolAddress((void**)&p_at,   g_at);
    cudaGetSymbolAddress((void**)&p_wq,   g_wq);
    cudaGetSymbolAddress((void**)&p_wo,   g_wo);

    cudaFuncSetAttribute(gemm_mma_kernel,
                         cudaFuncAttributeMaxDynamicSharedMemorySize, GSMEM);
    cudaFuncSetAttribute(attn_mma_kernel,
                         cudaFuncAttributeMaxDynamicSharedMemorySize, ATTN2_SMEM);

    // 0) operand prep
    cvt_wqkv_kernel<<<(QKVC * KDIM + 255) / 256, 256>>>(Wqkv, p_wq);
    cvt_kernel<<<(COUT * KDIM + 255) / 256, 256>>>(Wout, p_wo, COUT * KDIM);
    tsplit_kernel<<<dim3(S / 32, KDIM / 32, BATCH), dim3(32, 8)>>>(x, p_x);
    pool_x_kernel<<<BATCH * CIN, 256>>>(x, p_pool);
    xpose_kernel<<<dim3(KDIM / 32, NKVP / 32, BATCH), dim3(32, 8)>>>(p_pool, p_xp);

    // 1) Q = (0.125*Wq) @ x^T -> fp16 [B,512,1024]
    gemm_mma_kernel<<<dim3(S / 128, CIN / 128, BATCH), 256, GSMEM>>>(
        p_wq, p_x, nullptr, p_qh, nullptr, nullptr, S, 1);

    // 2) kv: K pre-act -> kvp fp16; V -> sigmoid fused -> vhg [b,h,d,n]
    gemm_mma_kernel<<<dim3(NKVP / 128, 1024 / 128, BATCH), 256, GSMEM>>>(
        p_wq + (size_t)CIN * KDIM, p_xp, nullptr, nullptr, p_vh, nullptr, NKVP, 2);

    // 3) K gate: sigmoid + tiled transpose -> khg [b,h,n,d]
    kvgate_k_kernel<<<dim3(NKV / 64, HEADS, BATCH), 256>>>(p_kvp, p_kh);

    // 4) tensor-core attention -> att fp16 [B,S,C]
    attn_mma_kernel<<<dim3(S / TQ, HEADS, BATCH), 256, ATTN2_SMEM>>>(
        p_qh, p_kh, p_vh, pos, p_at);

    // 5) out = Wout @ att^T + bout   [B,512,1024]
    gemm_mma_kernel<<<dim3(S / 128, COUT / 128, BATCH), 256, GSMEM>>>(
        p_wo, p_at, out, nullptr, nullptr, bout, S, 0);
}